// round 14
// baseline (speedup 1.0000x reference)
#include <cuda_runtime.h>
#include <cuda_fp16.h>
#include <math.h>

#define HH 256
#define WW 256
#define HW 65536
#define NB 8
#define NSLICE 24      // NB * 3 kept channels
#define NPIX (NB*HW)   // 524288
#define CAP 512        // INF = H + W in reference
#define BIG (1<<20)
#define RPB 4          // rows per block in k_main
#define NMAIN (NSLICE * (HH / RPB))   // 1536 blocks

// -------- device scratch (no allocations allowed) --------
// row-packed mask bits: [plane(2)][slice(24)][row(256)][word(8)] (bit = col within word)
__device__ unsigned g_row[2 * NSLICE * HH * 8];
// column-packed bits: [plane(2)][slice(24)][roww(8)][col(256)] (bit i = row roww*32+i)
__device__ unsigned g_bits[2 * NSLICE * 8 * WW];
// per-column word summaries: low byte zm (word has a 0), high byte om (word has a 1)
__device__ unsigned short g_msk[2 * NSLICE * WW];
__device__ __half   g_err[NSLICE * HW];          // (p - t)^2 per kept channel, fp16
__device__ int      g_cnt[2 * NSLICE];           // [0..23] p-counts, [24..47] t-counts
__device__ double   g_acc;
__device__ int      g_done;

// per-pixel softmax(4) + argmax(4) -> squared errors of ch 1..3 + 6 mask bits
__device__ __forceinline__ void pixel_work(float s0, float s1, float s2, float s3,
                                           float t0, float t1, float t2, float t3,
                                           float& e1o, float& e2o, float& e3o,
                                           unsigned& mk) {
    float m  = fmaxf(fmaxf(s0, s1), fmaxf(s2, s3));
    float e0 = __expf(s0 - m), e1 = __expf(s1 - m), e2 = __expf(s2 - m), e3 = __expf(s3 - m);
    float inv = __fdividef(1.0f, e0 + e1 + e2 + e3);
    float p1 = e1 * inv, p2 = e2 * inv, p3 = e3 * inv;

    int lab = 0; float best = t0;            // first-index-wins (matches jnp.argmax)
    if (t1 > best) { best = t1; lab = 1; }
    if (t2 > best) { best = t2; lab = 2; }
    if (t3 > best) { best = t3; lab = 3; }

    float g1 = (lab == 1) ? 1.0f : 0.0f;
    float g2 = (lab == 2) ? 1.0f : 0.0f;
    float g3 = (lab == 3) ? 1.0f : 0.0f;
    e1o = (p1 - g1) * (p1 - g1);
    e2o = (p2 - g2) * (p2 - g2);
    e3o = (p3 - g3) * (p3 - g3);

    mk = 0;
    if (p1 > 0.5f) mk |= 1u;
    if (p2 > 0.5f) mk |= 2u;
    if (p3 > 0.5f) mk |= 4u;
    mk |= ((unsigned)g1 << 3) | ((unsigned)g2 << 4) | ((unsigned)g3 << 5);
}

// -------- kernel 1: softmax + argmax + err + direct-ballot row-packing --------
// Vertical pixel pair per thread: (2R, col) and (2R+1, col). Block = 2-row
// stripe (grid 1024). Warp = 32 consecutive columns -> ballots ARE row words.
__global__ void __launch_bounds__(256) k_prep(const float* __restrict__ S,
                                              const float* __restrict__ T) {
    if (blockIdx.x == 0) {                      // accumulators consumed only by LATER kernels
        if (threadIdx.x < 2 * NSLICE) g_cnt[threadIdx.x] = 0;
        if (threadIdx.x == 2 * NSLICE) { g_acc = 0.0; g_done = 0; }
    }

    int tid  = threadIdx.x;
    int b    = blockIdx.x >> 7;                 // image
    int row0 = (blockIdx.x & 127) * 2;          // first of 2 rows
    int lane = tid & 31;
    int wrd  = tid >> 5;                        // word index within the row
    int pix0 = row0 * WW + tid;
    int pix1 = pix0 + WW;

    const float* s = S + (size_t)b * 4 * HW;
    const float* t = T + (size_t)b * 4 * HW;
    float sa0 = s[pix0], sa1 = s[pix0 + HW], sa2 = s[pix0 + 2 * HW], sa3 = s[pix0 + 3 * HW];
    float sb0 = s[pix1], sb1 = s[pix1 + HW], sb2 = s[pix1 + 2 * HW], sb3 = s[pix1 + 3 * HW];
    float ta0 = t[pix0], ta1 = t[pix0 + HW], ta2 = t[pix0 + 2 * HW], ta3 = t[pix0 + 3 * HW];
    float tb0 = t[pix1], tb1 = t[pix1 + HW], tb2 = t[pix1 + 2 * HW], tb3 = t[pix1 + 3 * HW];

    float a1, a2, a3, c1, c2, c3;
    unsigned m0, m1;
    pixel_work(sa0, sa1, sa2, sa3, ta0, ta1, ta2, ta3, a1, a2, a3, m0);
    pixel_work(sb0, sb1, sb2, sb3, tb0, tb1, tb2, tb3, c1, c2, c3, m1);

    int base = (b * 3) * HW + pix0;
    g_err[base]               = __float2half_rn(a1);
    g_err[base + HW]          = __float2half_rn(a2);
    g_err[base + 2 * HW]      = __float2half_rn(a3);
    g_err[base + WW]          = __float2half_rn(c1);
    g_err[base + HW + WW]     = __float2half_rn(c2);
    g_err[base + 2 * HW + WW] = __float2half_rn(c3);

    unsigned A0 = __ballot_sync(0xffffffffu, (m0 >> 0) & 1), C0 = __ballot_sync(0xffffffffu, (m1 >> 0) & 1);
    unsigned A1 = __ballot_sync(0xffffffffu, (m0 >> 1) & 1), C1 = __ballot_sync(0xffffffffu, (m1 >> 1) & 1);
    unsigned A2 = __ballot_sync(0xffffffffu, (m0 >> 2) & 1), C2 = __ballot_sync(0xffffffffu, (m1 >> 2) & 1);
    unsigned A3 = __ballot_sync(0xffffffffu, (m0 >> 3) & 1), C3 = __ballot_sync(0xffffffffu, (m1 >> 3) & 1);
    unsigned A4 = __ballot_sync(0xffffffffu, (m0 >> 4) & 1), C4 = __ballot_sync(0xffffffffu, (m1 >> 4) & 1);
    unsigned A5 = __ballot_sync(0xffffffffu, (m0 >> 5) & 1), C5 = __ballot_sync(0xffffffffu, (m1 >> 5) & 1);

    __shared__ unsigned stage[6][16];
    int beta = lane >> 1;
    int rl   = lane & 1;
    unsigned sA = (beta == 0) ? A0 : (beta == 1) ? A1 : (beta == 2) ? A2
                : (beta == 3) ? A3 : (beta == 4) ? A4 : A5;
    unsigned sC = (beta == 0) ? C0 : (beta == 1) ? C1 : (beta == 2) ? C2
                : (beta == 3) ? C3 : (beta == 4) ? C4 : C5;
    if (lane < 12) stage[beta][rl * 8 + wrd] = rl ? sC : sA;
    __syncthreads();

    if (tid < 96) {
        int c  = tid >> 4;                       // plane 0..5
        int i  = tid & 15;                       // rowlocal*8 + w
        int P  = (c >= 3) ? 1 : 0;
        int cc = c - 3 * P;
        int sl = b * 3 + cc;
        g_row[((size_t)(P * NSLICE + sl) * HH + row0) * 8 + i] = stage[c][i];
    }
}

// -------- kernel 2: transpose + per-column zm/om summaries + counts --------
// block = one plane-slice (48 blocks). Warp W transposes row-word W for all
// 256 columns; then each thread owns one column: zm/om masks + g_bits store.
__global__ void __launch_bounds__(256) k_trans() {
    int tid  = threadIdx.x;
    int lane = tid & 31;
    int W    = tid >> 5;          // warp = dest row-word
    int ps   = blockIdx.x;        // plane*NSLICE + slice, 0..47

    __shared__ unsigned stage[256 * 9];  // padded row-major copy
    __shared__ unsigned colw[8][WW];     // transposed [word][col]

    #pragma unroll
    for (int k = 0; k < 8; k++) {
        int idx = k * 256 + tid;            // coalesced
        int r = idx >> 3, w = idx & 7;
        stage[r * 9 + w] = g_row[(size_t)ps * HH * 8 + idx];
    }
    __syncthreads();

    #pragma unroll
    for (int C = 0; C < 8; C++) {
        unsigned in = stage[(32 * W + lane) * 9 + C];
        unsigned outw = 0;
        #pragma unroll
        for (int k = 0; k < 32; k++) {
            unsigned bal = __ballot_sync(0xffffffffu, (in >> k) & 1u);
            if (lane == k) outw = bal;
        }
        colw[W][32 * C + lane] = outw;
    }
    __syncthreads();

    // per-column pass: masks + count + publish column words
    unsigned cw[8];
    unsigned zm = 0, om = 0;
    int cnt = 0;
    #pragma unroll
    for (int w = 0; w < 8; w++) {
        cw[w] = colw[w][tid];
        zm |= (cw[w] != 0xFFFFFFFFu ? 1u : 0u) << w;
        om |= (cw[w] != 0u ? 1u : 0u) << w;
        cnt += __popc(cw[w]);
    }
    g_msk[ps * WW + tid] = (unsigned short)(zm | (om << 8));
    #pragma unroll
    for (int w = 0; w < 8; w++)
        g_bits[(size_t)ps * 8 * WW + w * WW + tid] = cw[w];

    int tot = __reduce_add_sync(0xffffffffu, cnt);
    if (lane == 0) atomicAdd(&g_cnt[ps], tot);
}

// adaptive exact search (G >= 0; best = G[j] >= 1; if best <= 1 nothing beats it)
__device__ __forceinline__ int edt_search(const int* __restrict__ G, int j) {
    int best = G[j];
    if (best <= 1) return best;
    int a = G[max(j - 1, 0)] + 1;
    int b = G[min(j + 1, WW - 1)] + 1;
    best = min(best, min(a, b));
    if (best > 4) {
        for (int d = 2; d < WW; d++) {
            int dd = d * d;
            if (dd >= best) break;
            int jm = j - d, jp = j + d;
            if (jm >= 0) best = min(best, G[jm] + dd);
            if (jp < WW) best = min(best, G[jp] + dd);
        }
    }
    return best;
}

// mask-directed fallbacks: zm/om say which words contain a 0/1; one predicated
// load per quantity fetches exactly the right word (L1-hot, independent).
__device__ __forceinline__ void fb_from_masks(const unsigned* __restrict__ P, int j, int w0,
                                              unsigned zm, unsigned om,
                                              int& fb0, int& fb1, int& la0, int& la1) {
    unsigned hiM = 0xFFFFu << (w0 + 1);
    unsigned loM = (1u << w0) - 1u;
    unsigned e;
    e = zm & hiM; fb0 = BIG;
    if (e) { int wz = __ffs(e) - 1; fb0 = wz * 32 + __ffs(~P[wz * WW + j]) - 1; }
    e = om & hiM; fb1 = BIG;
    if (e) { int wz = __ffs(e) - 1; fb1 = wz * 32 + __ffs(P[wz * WW + j]) - 1; }
    e = zm & loM; la0 = -BIG;
    if (e) { int wz = 31 - __clz(e); la0 = wz * 32 + 31 - __clz(~P[wz * WW + j]); }
    e = om & loM; la1 = -BIG;
    if (e) { int wz = 31 - __clz(e); la1 = wz * 32 + 31 - __clz(P[wz * WW + j]); }
}

// per-row vertical distances from register word + precomputed fallbacks
__device__ __forceinline__ void vrow(unsigned cur, int br, int R,
                                     int fb0, int fb1, int la0, int la1,
                                     int& d0, int& d1) {
    unsigned hi = 0xFFFFFFFFu << br;
    unsigned lo = 0xFFFFFFFFu >> (31 - br);
    unsigned nc = ~cur;

    unsigned x0 = nc & hi;
    int dn0 = x0 ? (__ffs(x0) - 1 - br) : (fb0 - R);
    unsigned y0 = nc & lo;
    int up0 = y0 ? (br - (31 - __clz(y0))) : (R - la0);
    d0 = min(min(dn0, up0), CAP);

    unsigned x1 = cur & hi;
    int dn1 = x1 ? (__ffs(x1) - 1 - br) : (fb1 - R);
    unsigned y1 = cur & lo;
    int up1 = y1 ? (br - (31 - __clz(y1))) : (R - la1);
    d1 = min(min(dn1, up1), CAP);
}

// -------- kernel 3: fused vertical+horizontal EDT + loss + finalize --------
// block = (slice, 4-row band); grid = 24*64 = 1536
__global__ void __launch_bounds__(256) k_main(float* __restrict__ out) {
    int tid  = threadIdx.x;
    int s    = blockIdx.x >> 6;    // slice 0..23
    int band = blockIdx.x & 63;    // 4-row band 0..63
    int j    = tid;                // column
    int w0   = band >> 3;          // word holding all 4 rows
    int bb   = (band & 7) * 4;     // bit base within word

    // prefetch scalars early (overlap the vrow/STS phase)
    const __half* erow = g_err + (size_t)s * HW + (size_t)band * RPB * WW + j;
    float err0 = __half2float(erow[0 * WW]);
    float err1 = __half2float(erow[1 * WW]);
    float err2 = __half2float(erow[2 * WW]);
    float err3 = __half2float(erow[3 * WW]);
    int cp = g_cnt[s], ct = g_cnt[NSLICE + s];
    unsigned mp = g_msk[s * WW + j];
    unsigned mt = g_msk[(NSLICE + s) * WW + j];

    const unsigned* Pp = g_bits + (size_t)(0 * NSLICE + s) * 8 * WW;
    const unsigned* Pt = g_bits + (size_t)(1 * NSLICE + s) * 8 * WW;

    unsigned curp = Pp[w0 * WW + j];
    unsigned curt = Pt[w0 * WW + j];
    int fb0p, fb1p, la0p, la1p, fb0t, fb1t, la0t, la1t;
    fb_from_masks(Pp, j, w0, mp & 0xFFu, (mp >> 8) & 0xFFu, fb0p, fb1p, la0p, la1p);
    fb_from_masks(Pt, j, w0, mt & 0xFFu, (mt >> 8) & 0xFFu, fb0t, fb1t, la0t, la1t);

    __shared__ int G[RPB][4][WW];
    #pragma unroll
    for (int r = 0; r < RPB; r++) {
        int br = bb + r;
        int R  = band * RPB + r;
        int d0, d1;
        vrow(curp, br, R, fb0p, fb1p, la0p, la1p, d0, d1);
        G[r][0][j] = d0 * d0;
        G[r][1][j] = d1 * d1;
        vrow(curt, br, R, fb0t, fb1t, la0t, la1t, d0, d1);
        G[r][2][j] = d0 * d0;
        G[r][3][j] = d1 * d1;
    }
    __syncthreads();               // ONE barrier per block

    float vp = (cp > 0 && cp < HW) ? 1.0f : 0.0f;
    float vt = (ct > 0 && ct < HW) ? 1.0f : 0.0f;
    float errs[RPB] = {err0, err1, err2, err3};

    float acc = 0.0f;
    #pragma unroll
    for (int r = 0; r < RPB; r++) {
        int br = bb + r;
        int p_true = (curp >> br) & 1;
        int t_true = (curt >> br) & 1;
        int dp = edt_search(&G[r][p_true ? 0 : 1][0], j);
        int dt = edt_search(&G[r][t_true ? 2 : 3][0], j);
        acc += errs[r] * ((float)dp * vp + (float)dt * vt);
    }

    // block reduction -> double atomic (once per block)
    #pragma unroll
    for (int o = 16; o; o >>= 1) acc += __shfl_down_sync(0xffffffffu, acc, o);
    __shared__ float wsum[8];
    if ((tid & 31) == 0) wsum[tid >> 5] = acc;
    __syncthreads();
    if (tid == 0) {
        float ssum = 0.0f;
        #pragma unroll
        for (int w = 0; w < 8; w++) ssum += wsum[w];
        atomicAdd(&g_acc, (double)ssum);
        __threadfence();
        int ticket = atomicAdd(&g_done, 1);
        if (ticket == NMAIN - 1) {             // last block finalizes
            double total = atomicAdd(&g_acc, 0.0);
            double mean  = total / (double)(NSLICE * HW);
            out[0] = (float)log(mean + 1.0);
        }
    }
}

extern "C" void kernel_launch(void* const* d_in, const int* in_sizes, int n_in,
                              void* d_out, int out_size) {
    const float* S = (const float*)d_in[0];     // preds_S (8,4,256,256)
    const float* T = (const float*)d_in[1];     // preds_T (8,4,256,256)
    (void)in_sizes; (void)n_in; (void)out_size; // target (d_in[2]) unused by reference

    k_prep<<<NB * HH / 2, 256>>>(S, T);
    k_trans<<<2 * NSLICE, 256>>>();
    k_main<<<NMAIN, 256>>>((float*)d_out);
}

// round 15
// speedup vs baseline: 1.1441x; 1.1441x over previous
#include <cuda_runtime.h>
#include <cuda_fp16.h>
#include <math.h>

#define HH 256
#define WW 256
#define HW 65536
#define NB 8
#define NSLICE 24      // NB * 3 kept channels
#define NPIX (NB*HW)   // 524288
#define CAP 512        // INF = H + W in reference
#define BIG (1<<20)
#define RPB 4          // rows per block in k_main
#define NMAIN (NSLICE * (HH / RPB))   // 1536 blocks

// -------- device scratch (no allocations allowed) --------
// row-packed mask bits: [plane(2)][slice(24)][row(256)][word(8)] (bit = col within word)
__device__ unsigned g_row[2 * NSLICE * HH * 8];
// column-packed bits: [plane(2)][slice(24)][roww(8)][col(256)] (bit i = row roww*32+i)
__device__ unsigned g_bits[2 * NSLICE * 8 * WW];
__device__ __half   g_err[NSLICE * HW];          // (p - t)^2 per kept channel, fp16
__device__ int      g_cnt[2 * NSLICE];           // [0..23] p-counts, [24..47] t-counts
__device__ double   g_acc;
__device__ int      g_done;

// per-pixel softmax(4) + argmax(4) -> squared errors of ch 1..3 + 6 mask bits
__device__ __forceinline__ void pixel_work(float s0, float s1, float s2, float s3,
                                           float t0, float t1, float t2, float t3,
                                           float& e1o, float& e2o, float& e3o,
                                           unsigned& mk) {
    float m  = fmaxf(fmaxf(s0, s1), fmaxf(s2, s3));
    float e0 = __expf(s0 - m), e1 = __expf(s1 - m), e2 = __expf(s2 - m), e3 = __expf(s3 - m);
    float inv = __fdividef(1.0f, e0 + e1 + e2 + e3);   // validated in R14: -0.3us, no acc cost
    float p1 = e1 * inv, p2 = e2 * inv, p3 = e3 * inv;

    int lab = 0; float best = t0;            // first-index-wins (matches jnp.argmax)
    if (t1 > best) { best = t1; lab = 1; }
    if (t2 > best) { best = t2; lab = 2; }
    if (t3 > best) { best = t3; lab = 3; }

    float g1 = (lab == 1) ? 1.0f : 0.0f;
    float g2 = (lab == 2) ? 1.0f : 0.0f;
    float g3 = (lab == 3) ? 1.0f : 0.0f;
    e1o = (p1 - g1) * (p1 - g1);
    e2o = (p2 - g2) * (p2 - g2);
    e3o = (p3 - g3) * (p3 - g3);

    mk = 0;
    if (p1 > 0.5f) mk |= 1u;
    if (p2 > 0.5f) mk |= 2u;
    if (p3 > 0.5f) mk |= 4u;
    mk |= ((unsigned)g1 << 3) | ((unsigned)g2 << 4) | ((unsigned)g3 << 5);
}

// -------- kernel 1: softmax + argmax + err + direct-ballot row-packing --------
// Vertical pixel pair per thread: (2R, col) and (2R+1, col). Block = 2-row
// stripe (grid 1024). Warp = 32 consecutive columns -> ballots ARE row words.
__global__ void __launch_bounds__(256) k_prep(const float* __restrict__ S,
                                              const float* __restrict__ T) {
    if (blockIdx.x == 0) {                      // accumulators consumed only by LATER kernels
        if (threadIdx.x < 2 * NSLICE) g_cnt[threadIdx.x] = 0;
        if (threadIdx.x == 2 * NSLICE) { g_acc = 0.0; g_done = 0; }
    }

    int tid  = threadIdx.x;
    int b    = blockIdx.x >> 7;                 // image
    int row0 = (blockIdx.x & 127) * 2;          // first of 2 rows
    int lane = tid & 31;
    int wrd  = tid >> 5;                        // word index within the row
    int pix0 = row0 * WW + tid;
    int pix1 = pix0 + WW;

    const float* s = S + (size_t)b * 4 * HW;
    const float* t = T + (size_t)b * 4 * HW;
    // 16 independent coalesced loads (max MLP)
    float sa0 = s[pix0], sa1 = s[pix0 + HW], sa2 = s[pix0 + 2 * HW], sa3 = s[pix0 + 3 * HW];
    float sb0 = s[pix1], sb1 = s[pix1 + HW], sb2 = s[pix1 + 2 * HW], sb3 = s[pix1 + 3 * HW];
    float ta0 = t[pix0], ta1 = t[pix0 + HW], ta2 = t[pix0 + 2 * HW], ta3 = t[pix0 + 3 * HW];
    float tb0 = t[pix1], tb1 = t[pix1 + HW], tb2 = t[pix1 + 2 * HW], tb3 = t[pix1 + 3 * HW];

    float a1, a2, a3, c1, c2, c3;
    unsigned m0, m1;
    pixel_work(sa0, sa1, sa2, sa3, ta0, ta1, ta2, ta3, a1, a2, a3, m0);
    pixel_work(sb0, sb1, sb2, sb3, tb0, tb1, tb2, tb3, c1, c2, c3, m1);

    int base = (b * 3) * HW + pix0;
    g_err[base]               = __float2half_rn(a1);
    g_err[base + HW]          = __float2half_rn(a2);
    g_err[base + 2 * HW]      = __float2half_rn(a3);
    g_err[base + WW]          = __float2half_rn(c1);
    g_err[base + HW + WW]     = __float2half_rn(c2);
    g_err[base + 2 * HW + WW] = __float2half_rn(c3);

    // 12 ballots: 6 planes x 2 rows; each IS a packed row word for this warp's columns
    unsigned A0 = __ballot_sync(0xffffffffu, (m0 >> 0) & 1), C0 = __ballot_sync(0xffffffffu, (m1 >> 0) & 1);
    unsigned A1 = __ballot_sync(0xffffffffu, (m0 >> 1) & 1), C1 = __ballot_sync(0xffffffffu, (m1 >> 1) & 1);
    unsigned A2 = __ballot_sync(0xffffffffu, (m0 >> 2) & 1), C2 = __ballot_sync(0xffffffffu, (m1 >> 2) & 1);
    unsigned A3 = __ballot_sync(0xffffffffu, (m0 >> 3) & 1), C3 = __ballot_sync(0xffffffffu, (m1 >> 3) & 1);
    unsigned A4 = __ballot_sync(0xffffffffu, (m0 >> 4) & 1), C4 = __ballot_sync(0xffffffffu, (m1 >> 4) & 1);
    unsigned A5 = __ballot_sync(0xffffffffu, (m0 >> 5) & 1), C5 = __ballot_sync(0xffffffffu, (m1 >> 5) & 1);

    // stage[plane][rowlocal*8 + word] = 96 words; lanes 0..11 store (beta, rl)
    __shared__ unsigned stage[6][16];
    int beta = lane >> 1;
    int rl   = lane & 1;
    unsigned sA = (beta == 0) ? A0 : (beta == 1) ? A1 : (beta == 2) ? A2
                : (beta == 3) ? A3 : (beta == 4) ? A4 : A5;
    unsigned sC = (beta == 0) ? C0 : (beta == 1) ? C1 : (beta == 2) ? C2
                : (beta == 3) ? C3 : (beta == 4) ? C4 : C5;
    if (lane < 12) stage[beta][rl * 8 + wrd] = rl ? sC : sA;
    __syncthreads();

    // 6 chunks of 16 contiguous words (rows row0, row0+1 adjacent in g_row)
    if (tid < 96) {
        int c  = tid >> 4;                       // plane 0..5
        int i  = tid & 15;                       // rowlocal*8 + w
        int P  = (c >= 3) ? 1 : 0;
        int cc = c - 3 * P;
        int sl = b * 3 + cc;
        g_row[((size_t)(P * NSLICE + sl) * HH + row0) * 8 + i] = stage[c][i];
    }
}

// -------- kernel 2: 32x32 bit-matrix transpose (coalesced) + counts --------
// grid = 384: one (ps, W) group per block; 8 warp-tiles via ballot.
__global__ void __launch_bounds__(256) k_trans() {
    int tid  = threadIdx.x;
    int lane = tid & 31;
    int ps = blockIdx.x >> 3;     // plane*NSLICE + slice, 0..47
    int W  = blockIdx.x & 7;      // dest row-word

    __shared__ unsigned tile[32 * 9];   // padded: bank-conflict-free column reads
    {
        int r = tid >> 3, w = tid & 7;
        // addr = ps*2048 + W*256 + tid -> perfectly coalesced
        tile[r * 9 + w] = g_row[((size_t)ps * HH + 32 * W + r) * 8 + w];
    }
    __syncthreads();

    int C = tid >> 5;             // warp = source column-word
    unsigned in = tile[lane * 9 + C];
    int c = __reduce_add_sync(0xffffffffu, __popc(in));
    if (lane == 0) atomicAdd(&g_cnt[ps], c);

    unsigned outw = 0;
    #pragma unroll
    for (int k = 0; k < 32; k++) {
        unsigned bal = __ballot_sync(0xffffffffu, (in >> k) & 1u);
        if (lane == k) outw = bal;
    }
    g_bits[(size_t)ps * 8 * WW + W * WW + 32 * C + lane] = outw;
}

// adaptive exact search. Facts: G >= 0 everywhere, best = G[j] >= 1 (selected
// array never contains the own pixel). If best <= 1 no candidate G[k]+d^2 can
// beat it (d^2 >= 1). Unconditional d=1 probe (clamped = over-estimate, safe),
// then rare dependent tail from d=2 (only if best > 4).
__device__ __forceinline__ int edt_search(const int* __restrict__ G, int j) {
    int best = G[j];
    if (best <= 1) return best;
    int a = G[max(j - 1, 0)] + 1;
    int b = G[min(j + 1, WW - 1)] + 1;
    best = min(best, min(a, b));
    if (best > 4) {
        for (int d = 2; d < WW; d++) {
            int dd = d * d;
            if (dd >= best) break;
            int jm = j - d, jp = j + d;
            if (jm >= 0) best = min(best, G[jm] + dd);
            if (jp < WW) best = min(best, G[jp] + dd);
        }
    }
    return best;
}

// on-demand out-of-word fallbacks for one plane/column (early-break; usually 1 iter)
__device__ __forceinline__ void fallbacks(const unsigned* __restrict__ P, int j, int w0,
                                          int& fb0, int& fb1, int& la0, int& la1) {
    fb0 = BIG; fb1 = BIG;
    for (int w = w0 + 1; w < 8 && (fb0 == BIG || fb1 == BIG); w++) {
        unsigned ww = P[w * WW + j];
        if (fb0 == BIG && ~ww) fb0 = w * 32 + __ffs(~ww) - 1;
        if (fb1 == BIG &&  ww) fb1 = w * 32 + __ffs(ww) - 1;
    }
    la0 = -BIG; la1 = -BIG;
    for (int w = w0 - 1; w >= 0 && (la0 == -BIG || la1 == -BIG); w--) {
        unsigned ww = P[w * WW + j];
        if (la0 == -BIG && ~ww) la0 = w * 32 + 31 - __clz(~ww);
        if (la1 == -BIG &&  ww) la1 = w * 32 + 31 - __clz(ww);
    }
}

// per-row vertical distances from register word + precomputed fallbacks
__device__ __forceinline__ void vrow(unsigned cur, int br, int R,
                                     int fb0, int fb1, int la0, int la1,
                                     int& d0, int& d1) {
    unsigned hi = 0xFFFFFFFFu << br;
    unsigned lo = 0xFFFFFFFFu >> (31 - br);
    unsigned nc = ~cur;

    unsigned x0 = nc & hi;
    int dn0 = x0 ? (__ffs(x0) - 1 - br) : (fb0 - R);
    unsigned y0 = nc & lo;
    int up0 = y0 ? (br - (31 - __clz(y0))) : (R - la0);
    d0 = min(min(dn0, up0), CAP);

    unsigned x1 = cur & hi;
    int dn1 = x1 ? (__ffs(x1) - 1 - br) : (fb1 - R);
    unsigned y1 = cur & lo;
    int up1 = y1 ? (br - (31 - __clz(y1))) : (R - la1);
    d1 = min(min(dn1, up1), CAP);
}

// -------- kernel 3: fused vertical+horizontal EDT + loss + finalize --------
// block = (slice, 4-row band); grid = 24*64 = 1536
__global__ void __launch_bounds__(256) k_main(float* __restrict__ out) {
    int tid  = threadIdx.x;
    int s    = blockIdx.x >> 6;    // slice 0..23
    int band = blockIdx.x & 63;    // 4-row band 0..63
    int j    = tid;                // column
    int w0   = band >> 3;          // word holding all 4 rows
    int bb   = (band & 7) * 4;     // bit base within word

    // prefetch scalars early: err (L2) + counts overlap the vrow/STS phase
    const __half* erow = g_err + (size_t)s * HW + (size_t)band * RPB * WW + j;
    float err0 = __half2float(erow[0 * WW]);
    float err1 = __half2float(erow[1 * WW]);
    float err2 = __half2float(erow[2 * WW]);
    float err3 = __half2float(erow[3 * WW]);
    int cp = g_cnt[s], ct = g_cnt[NSLICE + s];

    const unsigned* Pp = g_bits + (size_t)(0 * NSLICE + s) * 8 * WW;
    const unsigned* Pt = g_bits + (size_t)(1 * NSLICE + s) * 8 * WW;

    unsigned curp = Pp[w0 * WW + j];
    unsigned curt = Pt[w0 * WW + j];
    int fb0p, fb1p, la0p, la1p, fb0t, fb1t, la0t, la1t;
    fallbacks(Pp, j, w0, fb0p, fb1p, la0p, la1p);
    fallbacks(Pt, j, w0, fb0t, fb1t, la0t, la1t);

    __shared__ int G[RPB][4][WW];
    #pragma unroll
    for (int r = 0; r < RPB; r++) {
        int br = bb + r;
        int R  = band * RPB + r;
        int d0, d1;
        vrow(curp, br, R, fb0p, fb1p, la0p, la1p, d0, d1);
        G[r][0][j] = d0 * d0;
        G[r][1][j] = d1 * d1;
        vrow(curt, br, R, fb0t, fb1t, la0t, la1t, d0, d1);
        G[r][2][j] = d0 * d0;
        G[r][3][j] = d1 * d1;
    }
    __syncthreads();               // ONE barrier per block

    float vp = (cp > 0 && cp < HW) ? 1.0f : 0.0f;
    float vt = (ct > 0 && ct < HW) ? 1.0f : 0.0f;
    float errs[RPB] = {err0, err1, err2, err3};

    float acc = 0.0f;
    #pragma unroll
    for (int r = 0; r < RPB; r++) {
        int br = bb + r;
        int p_true = (curp >> br) & 1;
        int t_true = (curt >> br) & 1;
        int dp = edt_search(&G[r][p_true ? 0 : 1][0], j);
        int dt = edt_search(&G[r][t_true ? 2 : 3][0], j);
        acc += errs[r] * ((float)dp * vp + (float)dt * vt);
    }

    // block reduction -> double atomic (once per block)
    #pragma unroll
    for (int o = 16; o; o >>= 1) acc += __shfl_down_sync(0xffffffffu, acc, o);
    __shared__ float wsum[8];
    if ((tid & 31) == 0) wsum[tid >> 5] = acc;
    __syncthreads();
    if (tid == 0) {
        float ssum = 0.0f;
        #pragma unroll
        for (int w = 0; w < 8; w++) ssum += wsum[w];
        atomicAdd(&g_acc, (double)ssum);
        __threadfence();
        int ticket = atomicAdd(&g_done, 1);
        if (ticket == NMAIN - 1) {             // last block finalizes
            double total = atomicAdd(&g_acc, 0.0);
            double mean  = total / (double)(NSLICE * HW);
            out[0] = (float)log(mean + 1.0);
        }
    }
}

extern "C" void kernel_launch(void* const* d_in, const int* in_sizes, int n_in,
                              void* d_out, int out_size) {
    const float* S = (const float*)d_in[0];     // preds_S (8,4,256,256)
    const float* T = (const float*)d_in[1];     // preds_T (8,4,256,256)
    (void)in_sizes; (void)n_in; (void)out_size; // target (d_in[2]) unused by reference

    k_prep<<<NB * HH / 2, 256>>>(S, T);
    k_trans<<<384, 256>>>();
    k_main<<<NMAIN, 256>>>((float*)d_out);
}

// round 16
// speedup vs baseline: 1.1456x; 1.0013x over previous
#include <cuda_runtime.h>
#include <cuda_fp16.h>
#include <math.h>

#define HH 256
#define WW 256
#define HW 65536
#define NB 8
#define NSLICE 24      // NB * 3 kept channels
#define NPIX (NB*HW)   // 524288
#define CAP 512        // INF = H + W in reference
#define BIG (1<<20)
#define RPB 4          // rows per block in k_main
#define NMAIN (NSLICE * (HH / RPB))   // 1536 blocks

// -------- device scratch (no allocations allowed) --------
// row-packed mask bits: [plane(2)][slice(24)][row(256)][word(8)] (bit = col within word)
__device__ unsigned g_row[2 * NSLICE * HH * 8];
// column-packed bits: [plane(2)][slice(24)][roww(8)][col(256)] (bit i = row roww*32+i)
__device__ unsigned g_bits[2 * NSLICE * 8 * WW];
__device__ __half   g_err[NSLICE * HW];          // (p - t)^2 per kept channel, fp16
__device__ int      g_cnt[2 * NSLICE];           // [0..23] p-counts, [24..47] t-counts
__device__ double   g_acc;
__device__ int      g_done;

// per-pixel softmax(4) + argmax(4) -> squared errors of ch 1..3 + 6 mask bits
__device__ __forceinline__ void pixel_work(float s0, float s1, float s2, float s3,
                                           float t0, float t1, float t2, float t3,
                                           float& e1o, float& e2o, float& e3o,
                                           unsigned& mk) {
    float m  = fmaxf(fmaxf(s0, s1), fmaxf(s2, s3));
    float e0 = __expf(s0 - m), e1 = __expf(s1 - m), e2 = __expf(s2 - m), e3 = __expf(s3 - m);
    float inv = __fdividef(1.0f, e0 + e1 + e2 + e3);   // validated: -0.3us, no acc cost
    float p1 = e1 * inv, p2 = e2 * inv, p3 = e3 * inv;

    int lab = 0; float best = t0;            // first-index-wins (matches jnp.argmax)
    if (t1 > best) { best = t1; lab = 1; }
    if (t2 > best) { best = t2; lab = 2; }
    if (t3 > best) { best = t3; lab = 3; }

    float g1 = (lab == 1) ? 1.0f : 0.0f;
    float g2 = (lab == 2) ? 1.0f : 0.0f;
    float g3 = (lab == 3) ? 1.0f : 0.0f;
    e1o = (p1 - g1) * (p1 - g1);
    e2o = (p2 - g2) * (p2 - g2);
    e3o = (p3 - g3) * (p3 - g3);

    mk = 0;
    if (p1 > 0.5f) mk |= 1u;
    if (p2 > 0.5f) mk |= 2u;
    if (p3 > 0.5f) mk |= 4u;
    mk |= ((unsigned)g1 << 3) | ((unsigned)g2 << 4) | ((unsigned)g3 << 5);
}

// -------- kernel 1: softmax + argmax + err + direct-ballot row-packing --------
// Vertical pixel pair per thread: (2R, col) and (2R+1, col). Block = 2-row
// stripe (grid 1024). Warp = 32 consecutive columns -> ballots ARE row words.
__global__ void __launch_bounds__(256) k_prep(const float* __restrict__ S,
                                              const float* __restrict__ T) {
    if (blockIdx.x == 0) {                      // accumulators consumed only by LATER kernels
        if (threadIdx.x < 2 * NSLICE) g_cnt[threadIdx.x] = 0;
        if (threadIdx.x == 2 * NSLICE) { g_acc = 0.0; g_done = 0; }
    }

    int tid  = threadIdx.x;
    int b    = blockIdx.x >> 7;                 // image
    int row0 = (blockIdx.x & 127) * 2;          // first of 2 rows
    int lane = tid & 31;
    int wrd  = tid >> 5;                        // word index within the row
    int pix0 = row0 * WW + tid;
    int pix1 = pix0 + WW;

    const float* s = S + (size_t)b * 4 * HW;
    const float* t = T + (size_t)b * 4 * HW;
    // 16 independent coalesced loads (max MLP)
    float sa0 = s[pix0], sa1 = s[pix0 + HW], sa2 = s[pix0 + 2 * HW], sa3 = s[pix0 + 3 * HW];
    float sb0 = s[pix1], sb1 = s[pix1 + HW], sb2 = s[pix1 + 2 * HW], sb3 = s[pix1 + 3 * HW];
    float ta0 = t[pix0], ta1 = t[pix0 + HW], ta2 = t[pix0 + 2 * HW], ta3 = t[pix0 + 3 * HW];
    float tb0 = t[pix1], tb1 = t[pix1 + HW], tb2 = t[pix1 + 2 * HW], tb3 = t[pix1 + 3 * HW];

    float a1, a2, a3, c1, c2, c3;
    unsigned m0, m1;
    pixel_work(sa0, sa1, sa2, sa3, ta0, ta1, ta2, ta3, a1, a2, a3, m0);
    pixel_work(sb0, sb1, sb2, sb3, tb0, tb1, tb2, tb3, c1, c2, c3, m1);

    int base = (b * 3) * HW + pix0;
    g_err[base]               = __float2half_rn(a1);
    g_err[base + HW]          = __float2half_rn(a2);
    g_err[base + 2 * HW]      = __float2half_rn(a3);
    g_err[base + WW]          = __float2half_rn(c1);
    g_err[base + HW + WW]     = __float2half_rn(c2);
    g_err[base + 2 * HW + WW] = __float2half_rn(c3);

    // 12 ballots: 6 planes x 2 rows; each IS a packed row word for this warp's columns
    unsigned A0 = __ballot_sync(0xffffffffu, (m0 >> 0) & 1), C0 = __ballot_sync(0xffffffffu, (m1 >> 0) & 1);
    unsigned A1 = __ballot_sync(0xffffffffu, (m0 >> 1) & 1), C1 = __ballot_sync(0xffffffffu, (m1 >> 1) & 1);
    unsigned A2 = __ballot_sync(0xffffffffu, (m0 >> 2) & 1), C2 = __ballot_sync(0xffffffffu, (m1 >> 2) & 1);
    unsigned A3 = __ballot_sync(0xffffffffu, (m0 >> 3) & 1), C3 = __ballot_sync(0xffffffffu, (m1 >> 3) & 1);
    unsigned A4 = __ballot_sync(0xffffffffu, (m0 >> 4) & 1), C4 = __ballot_sync(0xffffffffu, (m1 >> 4) & 1);
    unsigned A5 = __ballot_sync(0xffffffffu, (m0 >> 5) & 1), C5 = __ballot_sync(0xffffffffu, (m1 >> 5) & 1);

    // stage[plane][rowlocal*8 + word] = 96 words; lanes 0..11 store (beta, rl)
    __shared__ unsigned stage[6][16];
    int beta = lane >> 1;
    int rl   = lane & 1;
    unsigned sA = (beta == 0) ? A0 : (beta == 1) ? A1 : (beta == 2) ? A2
                : (beta == 3) ? A3 : (beta == 4) ? A4 : A5;
    unsigned sC = (beta == 0) ? C0 : (beta == 1) ? C1 : (beta == 2) ? C2
                : (beta == 3) ? C3 : (beta == 4) ? C4 : C5;
    if (lane < 12) stage[beta][rl * 8 + wrd] = rl ? sC : sA;
    __syncthreads();

    // 6 chunks of 16 contiguous words (rows row0, row0+1 adjacent in g_row)
    if (tid < 96) {
        int c  = tid >> 4;                       // plane 0..5
        int i  = tid & 15;                       // rowlocal*8 + w
        int P  = (c >= 3) ? 1 : 0;
        int cc = c - 3 * P;
        int sl = b * 3 + cc;
        g_row[((size_t)(P * NSLICE + sl) * HH + row0) * 8 + i] = stage[c][i];
    }
}

// -------- kernel 2: 32x32 bit-matrix transpose (coalesced) + counts --------
// grid = 384: one (ps, W) group per block; 8 warp-tiles via ballot.
__global__ void __launch_bounds__(256) k_trans() {
#if __CUDA_ARCH__ >= 900
    cudaGridDependencySynchronize();   // PDL: wait for k_prep's g_row/g_cnt
#endif
    int tid  = threadIdx.x;
    int lane = tid & 31;
    int ps = blockIdx.x >> 3;     // plane*NSLICE + slice, 0..47
    int W  = blockIdx.x & 7;      // dest row-word

    __shared__ unsigned tile[32 * 9];   // padded: bank-conflict-free column reads
    {
        int r = tid >> 3, w = tid & 7;
        // addr = ps*2048 + W*256 + tid -> perfectly coalesced
        tile[r * 9 + w] = g_row[((size_t)ps * HH + 32 * W + r) * 8 + w];
    }
    __syncthreads();

    int C = tid >> 5;             // warp = source column-word
    unsigned in = tile[lane * 9 + C];
    int c = __reduce_add_sync(0xffffffffu, __popc(in));
    if (lane == 0) atomicAdd(&g_cnt[ps], c);

    unsigned outw = 0;
    #pragma unroll
    for (int k = 0; k < 32; k++) {
        unsigned bal = __ballot_sync(0xffffffffu, (in >> k) & 1u);
        if (lane == k) outw = bal;
    }
    g_bits[(size_t)ps * 8 * WW + W * WW + 32 * C + lane] = outw;
}

// adaptive exact search. Facts: G >= 0 everywhere, best = G[j] >= 1 (selected
// array never contains the own pixel). If best <= 1 no candidate G[k]+d^2 can
// beat it (d^2 >= 1). Unconditional d=1 probe (clamped = over-estimate, safe),
// then rare dependent tail from d=2 (only if best > 4).
__device__ __forceinline__ int edt_search(const int* __restrict__ G, int j) {
    int best = G[j];
    if (best <= 1) return best;
    int a = G[max(j - 1, 0)] + 1;
    int b = G[min(j + 1, WW - 1)] + 1;
    best = min(best, min(a, b));
    if (best > 4) {
        for (int d = 2; d < WW; d++) {
            int dd = d * d;
            if (dd >= best) break;
            int jm = j - d, jp = j + d;
            if (jm >= 0) best = min(best, G[jm] + dd);
            if (jp < WW) best = min(best, G[jp] + dd);
        }
    }
    return best;
}

// on-demand out-of-word fallbacks for one plane/column (early-break; usually 1 iter)
__device__ __forceinline__ void fallbacks(const unsigned* __restrict__ P, int j, int w0,
                                          int& fb0, int& fb1, int& la0, int& la1) {
    fb0 = BIG; fb1 = BIG;
    for (int w = w0 + 1; w < 8 && (fb0 == BIG || fb1 == BIG); w++) {
        unsigned ww = P[w * WW + j];
        if (fb0 == BIG && ~ww) fb0 = w * 32 + __ffs(~ww) - 1;
        if (fb1 == BIG &&  ww) fb1 = w * 32 + __ffs(ww) - 1;
    }
    la0 = -BIG; la1 = -BIG;
    for (int w = w0 - 1; w >= 0 && (la0 == -BIG || la1 == -BIG); w--) {
        unsigned ww = P[w * WW + j];
        if (la0 == -BIG && ~ww) la0 = w * 32 + 31 - __clz(~ww);
        if (la1 == -BIG &&  ww) la1 = w * 32 + 31 - __clz(ww);
    }
}

// per-row vertical distances from register word + precomputed fallbacks
__device__ __forceinline__ void vrow(unsigned cur, int br, int R,
                                     int fb0, int fb1, int la0, int la1,
                                     int& d0, int& d1) {
    unsigned hi = 0xFFFFFFFFu << br;
    unsigned lo = 0xFFFFFFFFu >> (31 - br);
    unsigned nc = ~cur;

    unsigned x0 = nc & hi;
    int dn0 = x0 ? (__ffs(x0) - 1 - br) : (fb0 - R);
    unsigned y0 = nc & lo;
    int up0 = y0 ? (br - (31 - __clz(y0))) : (R - la0);
    d0 = min(min(dn0, up0), CAP);

    unsigned x1 = cur & hi;
    int dn1 = x1 ? (__ffs(x1) - 1 - br) : (fb1 - R);
    unsigned y1 = cur & lo;
    int up1 = y1 ? (br - (31 - __clz(y1))) : (R - la1);
    d1 = min(min(dn1, up1), CAP);
}

// -------- kernel 3: fused vertical+horizontal EDT + loss + finalize --------
// block = (slice, 4-row band); grid = 24*64 = 1536
__global__ void __launch_bounds__(256) k_main(float* __restrict__ out) {
#if __CUDA_ARCH__ >= 900
    cudaGridDependencySynchronize();   // PDL: wait for k_trans's g_bits/g_cnt (and k_prep's g_err)
#endif
    int tid  = threadIdx.x;
    int s    = blockIdx.x >> 6;    // slice 0..23
    int band = blockIdx.x & 63;    // 4-row band 0..63
    int j    = tid;                // column
    int w0   = band >> 3;          // word holding all 4 rows
    int bb   = (band & 7) * 4;     // bit base within word

    // prefetch scalars early: err (L2) + counts overlap the vrow/STS phase
    const __half* erow = g_err + (size_t)s * HW + (size_t)band * RPB * WW + j;
    float err0 = __half2float(erow[0 * WW]);
    float err1 = __half2float(erow[1 * WW]);
    float err2 = __half2float(erow[2 * WW]);
    float err3 = __half2float(erow[3 * WW]);
    int cp = g_cnt[s], ct = g_cnt[NSLICE + s];

    const unsigned* Pp = g_bits + (size_t)(0 * NSLICE + s) * 8 * WW;
    const unsigned* Pt = g_bits + (size_t)(1 * NSLICE + s) * 8 * WW;

    unsigned curp = Pp[w0 * WW + j];
    unsigned curt = Pt[w0 * WW + j];
    int fb0p, fb1p, la0p, la1p, fb0t, fb1t, la0t, la1t;
    fallbacks(Pp, j, w0, fb0p, fb1p, la0p, la1p);
    fallbacks(Pt, j, w0, fb0t, fb1t, la0t, la1t);

    __shared__ int G[RPB][4][WW];
    #pragma unroll
    for (int r = 0; r < RPB; r++) {
        int br = bb + r;
        int R  = band * RPB + r;
        int d0, d1;
        vrow(curp, br, R, fb0p, fb1p, la0p, la1p, d0, d1);
        G[r][0][j] = d0 * d0;
        G[r][1][j] = d1 * d1;
        vrow(curt, br, R, fb0t, fb1t, la0t, la1t, d0, d1);
        G[r][2][j] = d0 * d0;
        G[r][3][j] = d1 * d1;
    }
    __syncthreads();               // ONE barrier per block

    float vp = (cp > 0 && cp < HW) ? 1.0f : 0.0f;
    float vt = (ct > 0 && ct < HW) ? 1.0f : 0.0f;
    float errs[RPB] = {err0, err1, err2, err3};

    float acc = 0.0f;
    #pragma unroll
    for (int r = 0; r < RPB; r++) {
        int br = bb + r;
        int p_true = (curp >> br) & 1;
        int t_true = (curt >> br) & 1;
        int dp = edt_search(&G[r][p_true ? 0 : 1][0], j);
        int dt = edt_search(&G[r][t_true ? 2 : 3][0], j);
        acc += errs[r] * ((float)dp * vp + (float)dt * vt);
    }

    // block reduction -> double atomic (once per block)
    #pragma unroll
    for (int o = 16; o; o >>= 1) acc += __shfl_down_sync(0xffffffffu, acc, o);
    __shared__ float wsum[8];
    if ((tid & 31) == 0) wsum[tid >> 5] = acc;
    __syncthreads();
    if (tid == 0) {
        float ssum = 0.0f;
        #pragma unroll
        for (int w = 0; w < 8; w++) ssum += wsum[w];
        atomicAdd(&g_acc, (double)ssum);
        __threadfence();
        int ticket = atomicAdd(&g_done, 1);
        if (ticket == NMAIN - 1) {             // last block finalizes
            double total = atomicAdd(&g_acc, 0.0);
            double mean  = total / (double)(NSLICE * HW);
            out[0] = (float)log(mean + 1.0);
        }
    }
}

extern "C" void kernel_launch(void* const* d_in, const int* in_sizes, int n_in,
                              void* d_out, int out_size) {
    const float* S = (const float*)d_in[0];     // preds_S (8,4,256,256)
    const float* T = (const float*)d_in[1];     // preds_T (8,4,256,256)
    (void)in_sizes; (void)n_in; (void)out_size; // target (d_in[2]) unused by reference

    cudaLaunchAttribute at[1];
    at[0].id = cudaLaunchAttributeProgrammaticStreamSerialization;
    at[0].val.programmaticStreamSerializationAllowed = 1;

    cudaLaunchConfig_t cfg = {};
    cfg.blockDim = dim3(256, 1, 1);
    cfg.stream   = 0;                 // legacy default stream (same as <<<>>>)

    // k_prep: plain launch
    cfg.gridDim = dim3(NB * HH / 2, 1, 1);
    cfg.attrs = nullptr; cfg.numAttrs = 0;
    cudaLaunchKernelEx(&cfg, k_prep, S, T);

    // k_trans: PDL on k_prep
    cfg.gridDim = dim3(384, 1, 1);
    cfg.attrs = at; cfg.numAttrs = 1;
    cudaLaunchKernelEx(&cfg, k_trans);

    // k_main: PDL on k_trans
    cfg.gridDim = dim3(NMAIN, 1, 1);
    cudaLaunchKernelEx(&cfg, k_main, (float*)d_out);
}